// round 7
// baseline (speedup 1.0000x reference)
#include <cuda_runtime.h>
#include <cstring>

#define S_LEN 512
#define BATCH 64
#define IDIM  256
#define HID   512
#define ODIM  512    // 2*O

#define RSTR2 36     // sred row stride (floats): 144B, 16B-aligned, ~conflict-free

// ---------------- scratch (static device globals; no allocation) -------------
__device__ float    g_hs [(size_t)S_LEN * BATCH * HID];          // [S][B][H] -> GEMM2
__device__ float    g_hsT[(size_t)(S_LEN + 1) * 8 * HID * 8];    // [step][g*2+bh][k512][b8]
__device__ float    g_xT [(size_t)S_LEN * 8 * IDIM * 8];         // [s][g*2+bh][k256][b8]
__device__ unsigned g_blk[4 * 2 * 8 * 64];                       // [(g*2+bh)*8+blk]*64

// ---------------- packed f32x2 FMA (full-rate fp32 on sm_100a) ---------------
__device__ __forceinline__ float2 ffma2(float2 a, float2 b, float2 c) {
#if defined(__CUDA_ARCH__) && (__CUDA_ARCH__ >= 1000)
    unsigned long long au, bu, cu, du;
    memcpy(&au, &a, 8); memcpy(&bu, &b, 8); memcpy(&cu, &c, 8);
    asm("fma.rn.f32x2 %0, %1, %2, %3;" : "=l"(du) : "l"(au), "l"(bu), "l"(cu));
    float2 d; memcpy(&d, &du, 8);
    return d;
#else
    return make_float2(fmaf(a.x, b.x, c.x), fmaf(a.y, b.y, c.y));
#endif
}

__device__ __forceinline__ void poll_ge(const unsigned* a, unsigned need) {
    unsigned v;
    do {
        asm volatile("ld.acquire.gpu.global.u32 %0, [%1];" : "=r"(v) : "l"(a) : "memory");
    } while (v < need);
}

__device__ __forceinline__ float fast_sigmoid(float x) {
    return __fdividef(1.f, 1.f + __expf(-x));
}
__device__ __forceinline__ float fast_tanh(float x) {
    return __fdividef(2.f, 1.f + __expf(-2.f * x)) - 1.f;
}

// =============================================================================
// Prologue: x[b][s][k] -> g_xT[s][(grp*2+bh)][k][b8]
// =============================================================================
__global__ __launch_bounds__(256)
void transpose_x(const float* __restrict__ x)
{
    __shared__ float ts[16 * 260];
    const int tid = threadIdx.x;
    const int sg  = blockIdx.x;          // s*4 + grp
    const int s   = sg >> 2, grp = sg & 3;
    const int bb  = tid >> 4, kq = tid & 15;

    const float* src = x + ((size_t)(grp * 16 + bb) * S_LEN + s) * IDIM + kq * 16;
#pragma unroll
    for (int i = 0; i < 4; i++)
        *(float4*)(ts + bb * 260 + kq * 16 + 4 * i) = *(const float4*)(src + 4 * i);
    __syncthreads();

#pragma unroll
    for (int q = 0; q < 4; q++) {        // b = 4q..4q+3, bh = q>>1
        float4 o;
        o.x = ts[(4 * q + 0) * 260 + tid];
        o.y = ts[(4 * q + 1) * 260 + tid];
        o.z = ts[(4 * q + 2) * 260 + tid];
        o.w = ts[(4 * q + 3) * 260 + tid];
        *(float4*)(g_xT + ((size_t)sg * 2 + (q >> 1)) * 2048 + tid * 8 + (q & 1) * 4) = o;
    }
}

// =============================================================================
// Tiled GEMM (output projection): C[M][N] = A[M][K]*B[N][K]^T + bias[N]
// =============================================================================
template<int KDIM, int MODE>
__global__ __launch_bounds__(256, 2)
void gemm_tn(const float* __restrict__ A, const float* __restrict__ B,
             const float* __restrict__ bias, float* __restrict__ C)
{
    __shared__ float As[16 * 132];
    __shared__ float Bs[16 * 132];

    const int tid = threadIdx.x;
    const int m0 = blockIdx.y * 128;
    const int n0 = blockIdx.x * 128;
    const int lr = tid >> 2;
    const int lc = tid & 3;
    const int tx = tid & 15;
    const int ty = tid >> 4;

    const float* Ap = A + (size_t)(m0 + lr) * KDIM + lc * 4;
    const float* Bp = B + (size_t)(n0 + lr) * KDIM + lc * 4;

    float2 c2[8][4];
#pragma unroll
    for (int i = 0; i < 8; i++)
#pragma unroll
        for (int j = 0; j < 4; j++) c2[i][j] = make_float2(0.f, 0.f);

    float4 pa0 = *(const float4*)(Ap);
    float4 pa1 = *(const float4*)(Ap + (size_t)64 * KDIM);
    float4 pb0 = *(const float4*)(Bp);
    float4 pb1 = *(const float4*)(Bp + (size_t)64 * KDIM);

    const int KT = KDIM / 16;
    for (int kt = 0; kt < KT; kt++) {
        {
            const float* a0 = (const float*)&pa0;
            const float* a1 = (const float*)&pa1;
            const float* b0 = (const float*)&pb0;
            const float* b1 = (const float*)&pb1;
#pragma unroll
            for (int j = 0; j < 4; j++) {
                As[(lc * 4 + j) * 132 + lr]      = a0[j];
                As[(lc * 4 + j) * 132 + lr + 64] = a1[j];
                Bs[(lc * 4 + j) * 132 + lr]      = b0[j];
                Bs[(lc * 4 + j) * 132 + lr + 64] = b1[j];
            }
        }
        __syncthreads();
        if (kt + 1 < KT) {
            Ap += 16; Bp += 16;
            pa0 = *(const float4*)(Ap);
            pa1 = *(const float4*)(Ap + (size_t)64 * KDIM);
            pb0 = *(const float4*)(Bp);
            pb1 = *(const float4*)(Bp + (size_t)64 * KDIM);
        }
#pragma unroll
        for (int k = 0; k < 16; k++) {
            float4 a0 = *(const float4*)&As[k * 132 + ty * 4];
            float4 a1 = *(const float4*)&As[k * 132 + 64 + ty * 4];
            float4 b0 = *(const float4*)&Bs[k * 132 + tx * 4];
            float4 b1 = *(const float4*)&Bs[k * 132 + 64 + tx * 4];
            float av[8] = {a0.x, a0.y, a0.z, a0.w, a1.x, a1.y, a1.z, a1.w};
            float2 bv[4] = {{b0.x, b0.y}, {b0.z, b0.w}, {b1.x, b1.y}, {b1.z, b1.w}};
#pragma unroll
            for (int i = 0; i < 8; i++) {
                float2 ad = make_float2(av[i], av[i]);
#pragma unroll
                for (int j = 0; j < 4; j++) c2[i][j] = ffma2(ad, bv[j], c2[i][j]);
            }
        }
        __syncthreads();
    }

    int ncol[4];
    float2 bb[4];
#pragma unroll
    for (int j = 0; j < 4; j++) {
        ncol[j] = n0 + ((j < 2) ? (tx * 4 + 2 * j) : (64 + tx * 4 + 2 * (j - 2)));
        bb[j] = make_float2(bias[ncol[j]], bias[ncol[j] + 1]);
    }

#pragma unroll
    for (int i = 0; i < 8; i++) {
        int r = m0 + ((i < 4) ? (ty * 4 + i) : (64 + ty * 4 + (i - 4)));
        size_t rbase;
        if (MODE == 0) {
            rbase = (size_t)r * (3 * HID);
        } else {
            int s = r >> 6, b = r & 63;
            rbase = ((size_t)(b * S_LEN + s)) * ODIM;
        }
#pragma unroll
        for (int j = 0; j < 4; j++) {
            float2 v = make_float2(c2[i][j].x + bb[j].x, c2[i][j].y + bb[j].y);
            *(float2*)&C[rbase + ncol[j]] = v;
        }
    }
}

// =============================================================================
// Dual-chain fused GRU scan.
// 128 CTAs: pair = blk>>6 (groups 2p, 2p+1), slice = (blk&63)>>1 (16 j),
// bh = blk&1 (batches bh*8..+8 of each group). Same w_hh regs serve BOTH
// groups. Two interleaved chains: A-phase serial windows hidden by B-work.
// Exchange: per (group,bh) 32-CTA network, 8 blocks x 4 producers, monotonic
// counters, contiguous [k][b8] layouts.
// =============================================================================
__global__ __launch_bounds__(256, 1)
void gru_scan(const float* __restrict__ w_ih, const float* __restrict__ w_hh,
              const float* __restrict__ b_ih, const float* __restrict__ b_hh)
{
    extern __shared__ float sm[];
    float* shA  = sm;               // 4096 : h_A [k512][b8]
    float* shB  = sm + 4096;        // 4096 : h_B
    float* sred = sm + 8192;        // 9216 : partials 256 x RSTR2
    float* sxA  = sm + 17408;       // 2048 : x_A [k256][b8]
    float* sxB  = sm + 19456;       // 2048 : x_B
    float* sw   = sm + 21504;       // 12336: w_ih slice [48][257]

    const int tid   = threadIdx.x;
    const int lane  = tid & 31;
    const int wrp   = tid >> 5;
    const int pair  = blockIdx.x >> 6;
    const int sub   = blockIdx.x & 63;
    const int slice = sub >> 1;
    const int bh    = sub & 1;
    const int j0    = slice * 16;
    const int gA    = pair * 2;
    const int gB    = pair * 2 + 1;
    const int own_blk = slice >> 2;
    const int kI = tid >> 4, jI = tid & 15;
    const int jj = tid >> 3, bbat = tid & 7;       // gate ids (tid<128)

    // ---- w_hh register-resident (k = kI + 16*m), shared by both groups ----
    float w[3][32];
#pragma unroll
    for (int g = 0; g < 3; g++) {
        const float* p = w_hh + (size_t)(g * HID + j0 + jI) * HID + kI;
#pragma unroll
        for (int m = 0; m < 32; m++) w[g][m] = p[16 * m];
    }

    // ---- stage w_ih slice ---------------------------------------------------
    for (int i = tid; i < 48 * 256; i += 256) {
        int row = i >> 8, k = i & 255;
        int g = row >> 4, jr = row & 15;
        sw[row * 257 + k] = w_ih[(size_t)(g * HID + j0 + jr) * IDIM + k];
    }

    float bR = 0.f, bZ = 0.f, bIN = 0.f, bHN = 0.f;
    if (tid < 128) {
        bR  = b_ih[j0 + jj]       + b_hh[j0 + jj];
        bZ  = b_ih[HID + j0 + jj] + b_hh[HID + j0 + jj];
        bIN = b_ih[2 * HID + j0 + jj];
        bHN = b_hh[2 * HID + j0 + jj];
    }

    for (int i = tid; i < 8192; i += 256) sm[i] = 0.f;   // h0 = 0 (both groups)
    {   // stage x(0) for both groups
        const float4* a = (const float4*)(g_xT + ((size_t)gA * 2 + bh) * 2048);
        const float4* b = (const float4*)(g_xT + ((size_t)gB * 2 + bh) * 2048);
        ((float4*)sxA)[tid] = a[tid]; ((float4*)sxA)[tid + 256] = a[tid + 256];
        ((float4*)sxB)[tid] = b[tid]; ((float4*)sxB)[tid + 256] = b[tid + 256];
    }
    __syncthreads();

    const float* swr = sw + jI * 257        + kI * 16;
    const float* swz = sw + (16 + jI) * 257 + kI * 16;
    const float* swn = sw + (32 + jI) * 257 + kI * 16;

    unsigned* ctrA_own = &g_blk[((gA * 2 + bh) * 8 + own_blk) * 64];
    unsigned* ctrB_own = &g_blk[((gB * 2 + bh) * 8 + own_blk) * 64];
    const unsigned* ctrA_poll = &g_blk[((gA * 2 + bh) * 8 + wrp) * 64];
    const unsigned* ctrB_poll = &g_blk[((gB * 2 + bh) * 8 + wrp) * 64];

    for (int s = 0; s < S_LEN; s++) {
        const unsigned need = 4u * (unsigned)s;

        // ==== P1/P2: poll A + LDG h_A ====================================
        float4 ha0, ha1, ha2, ha3;
        if (s > 0) {
            if (lane == 0) poll_ge(ctrA_poll, need);
            __syncwarp();
            const float4* srcb =
                (const float4*)(g_hsT + ((size_t)s * 8 + gA * 2 + bh) * 4096) + wrp * 128 + lane;
            ha0 = srcb[0]; ha1 = srcb[32]; ha2 = srcb[64]; ha3 = srcb[96];
        }

        // ==== gi_A (hides LDG h_A) =======================================
        float2 acc[4][4];
#pragma unroll
        for (int p = 0; p < 4; p++)
#pragma unroll
            for (int g = 0; g < 4; g++) acc[p][g] = make_float2(0.f, 0.f);
        {
            const float* xr = sxA + kI * 128;
#pragma unroll 4
            for (int kk = 0; kk < 16; kk++) {
                float2 WR = {swr[kk], swr[kk]};
                float2 WZ = {swz[kk], swz[kk]};
                float2 WN = {swn[kk], swn[kk]};
#pragma unroll
                for (int p = 0; p < 4; p++) {
                    float2 x2 = *(const float2*)(xr + kk * 8 + 2 * p);
                    acc[p][0] = ffma2(x2, WR, acc[p][0]);
                    acc[p][1] = ffma2(x2, WZ, acc[p][1]);
                    acc[p][3] = ffma2(x2, WN, acc[p][3]);
                }
            }
        }

        // LDG x_A(s+1) prefetch (stored at P7)
        float4 xfA0, xfA1;
        if (s + 1 < S_LEN) {
            const float4* xs =
                (const float4*)(g_xT + (((size_t)(s + 1) * 4 + gA) * 2 + bh) * 2048);
            xfA0 = xs[tid]; xfA1 = xs[tid + 256];
        }

        if (s > 0) {
            float4* d = (float4*)shA + wrp * 128 + lane;
            d[0] = ha0; d[32] = ha1; d[64] = ha2; d[96] = ha3;
        }
        __syncthreads();                                   // bar1

        // ==== gh_A ========================================================
        if (s > 0) {
#pragma unroll
            for (int m = 0; m < 32; m++) {
                const float* hr = shA + (kI + 16 * m) * 8;
                float2 WR = {w[0][m], w[0][m]};
                float2 WZ = {w[1][m], w[1][m]};
                float2 WN = {w[2][m], w[2][m]};
#pragma unroll
                for (int p = 0; p < 4; p++) {
                    float2 h2 = *(const float2*)(hr + 2 * p);
                    acc[p][0] = ffma2(h2, WR, acc[p][0]);
                    acc[p][1] = ffma2(h2, WZ, acc[p][1]);
                    acc[p][2] = ffma2(h2, WN, acc[p][2]);
                }
            }
        }

        // ==== dump_A ======================================================
        {
            float* rp = sred + tid * RSTR2;
#pragma unroll
            for (int p = 0; p < 4; p++) {
                *(float4*)(rp + 8 * p) =
                    make_float4(acc[p][0].x, acc[p][1].x, acc[p][2].x, acc[p][3].x);
                *(float4*)(rp + 8 * p + 4) =
                    make_float4(acc[p][0].y, acc[p][1].y, acc[p][2].y, acc[p][3].y);
            }
        }
        __syncthreads();                                   // bar2

        // ==== poll B + LDG h_B (hidden under reduce_A + gi_B) ============
        float4 hb0, hb1, hb2, hb3;
        if (s > 0) {
            if (lane == 0) poll_ge(ctrB_poll, need);
            __syncwarp();
            const float4* srcb =
                (const float4*)(g_hsT + ((size_t)s * 8 + gB * 2 + bh) * 4096) + wrp * 128 + lane;
            hb0 = srcb[0]; hb1 = srcb[32]; hb2 = srcb[64]; hb3 = srcb[96];
        }

        // ==== reduce_A + gates_A (tid<128) ================================
        if (tid < 128) {
            float R = bR, Z = bZ, GN = 0.f, GI = bIN;
#pragma unroll
            for (int kc = 0; kc < 16; kc++) {
                float4 v = *(const float4*)(sred + (kc * 16 + jj) * RSTR2 + 4 * bbat);
                R += v.x; Z += v.y; GN += v.z; GI += v.w;
            }
            float r = fast_sigmoid(R);
            float z = fast_sigmoid(Z);
            float n = fast_tanh(GI + r * (GN + bHN));
            float hp = shA[(j0 + jj) * 8 + bbat];
            float hn = (1.f - z) * n + z * hp;
            g_hsT[((size_t)(s + 1) * 8 + gA * 2 + bh) * 4096 + (j0 + jj) * 8 + bbat] = hn;
            g_hs[((size_t)s * BATCH + gA * 16 + bh * 8 + bbat) * HID + j0 + jj] = hn;
        }

        // ==== gi_B (all threads; warps 4-7 start immediately) =============
#pragma unroll
        for (int p = 0; p < 4; p++)
#pragma unroll
            for (int g = 0; g < 4; g++) acc[p][g] = make_float2(0.f, 0.f);
        {
            const float* xr = sxB + kI * 128;
#pragma unroll 4
            for (int kk = 0; kk < 16; kk++) {
                float2 WR = {swr[kk], swr[kk]};
                float2 WZ = {swz[kk], swz[kk]};
                float2 WN = {swn[kk], swn[kk]};
#pragma unroll
                for (int p = 0; p < 4; p++) {
                    float2 x2 = *(const float2*)(xr + kk * 8 + 2 * p);
                    acc[p][0] = ffma2(x2, WR, acc[p][0]);
                    acc[p][1] = ffma2(x2, WZ, acc[p][1]);
                    acc[p][3] = ffma2(x2, WN, acc[p][3]);
                }
            }
        }

        // LDG x_B(s+1) prefetch (stored at P11)
        float4 xfB0, xfB1;
        if (s + 1 < S_LEN) {
            const float4* xs =
                (const float4*)(g_xT + (((size_t)(s + 1) * 4 + gB) * 2 + bh) * 2048);
            xfB0 = xs[tid]; xfB1 = xs[tid + 256];
        }
        __syncthreads();                                   // bar3

        if (tid == 0)
            asm volatile("red.release.gpu.global.add.u32 [%0], 1;" :: "l"(ctrA_own) : "memory");

        if (s > 0) {
            float4* d = (float4*)shB + wrp * 128 + lane;
            d[0] = hb0; d[32] = hb1; d[64] = hb2; d[96] = hb3;
        }
        if (s + 1 < S_LEN) {
            ((float4*)sxA)[tid] = xfA0; ((float4*)sxA)[tid + 256] = xfA1;
        }
        __syncthreads();                                   // bar4

        // ==== gh_B ========================================================
        if (s > 0) {
#pragma unroll
            for (int m = 0; m < 32; m++) {
                const float* hr = shB + (kI + 16 * m) * 8;
                float2 WR = {w[0][m], w[0][m]};
                float2 WZ = {w[1][m], w[1][m]};
                float2 WN = {w[2][m], w[2][m]};
#pragma unroll
                for (int p = 0; p < 4; p++) {
                    float2 h2 = *(const float2*)(hr + 2 * p);
                    acc[p][0] = ffma2(h2, WR, acc[p][0]);
                    acc[p][1] = ffma2(h2, WZ, acc[p][1]);
                    acc[p][2] = ffma2(h2, WN, acc[p][2]);
                }
            }
        }

        // ==== dump_B ======================================================
        {
            float* rp = sred + tid * RSTR2;
#pragma unroll
            for (int p = 0; p < 4; p++) {
                *(float4*)(rp + 8 * p) =
                    make_float4(acc[p][0].x, acc[p][1].x, acc[p][2].x, acc[p][3].x);
                *(float4*)(rp + 8 * p + 4) =
                    make_float4(acc[p][0].y, acc[p][1].y, acc[p][2].y, acc[p][3].y);
            }
        }
        __syncthreads();                                   // bar5

        // ==== reduce_B + gates_B (tid<128) ================================
        if (tid < 128) {
            float R = bR, Z = bZ, GN = 0.f, GI = bIN;
#pragma unroll
            for (int kc = 0; kc < 16; kc++) {
                float4 v = *(const float4*)(sred + (kc * 16 + jj) * RSTR2 + 4 * bbat);
                R += v.x; Z += v.y; GN += v.z; GI += v.w;
            }
            float r = fast_sigmoid(R);
            float z = fast_sigmoid(Z);
            float n = fast_tanh(GI + r * (GN + bHN));
            float hp = shB[(j0 + jj) * 8 + bbat];
            float hn = (1.f - z) * n + z * hp;
            g_hsT[((size_t)(s + 1) * 8 + gB * 2 + bh) * 4096 + (j0 + jj) * 8 + bbat] = hn;
            g_hs[((size_t)s * BATCH + gB * 16 + bh * 8 + bbat) * HID + j0 + jj] = hn;
        }
        __syncthreads();                                   // bar6

        if (tid == 0)
            asm volatile("red.release.gpu.global.add.u32 [%0], 1;" :: "l"(ctrB_own) : "memory");
        if (s + 1 < S_LEN) {
            ((float4*)sxB)[tid] = xfB0; ((float4*)sxB)[tid + 256] = xfB1;
        }
    }
}

// =============================================================================
extern "C" void kernel_launch(void* const* d_in, const int* in_sizes, int n_in,
                              void* d_out, int out_size)
{
    (void)in_sizes; (void)n_in; (void)out_size;
    const float* x     = (const float*)d_in[0];
    const float* w_ih  = (const float*)d_in[1];
    const float* w_hh  = (const float*)d_in[2];
    const float* b_ih  = (const float*)d_in[3];
    const float* b_hh  = (const float*)d_in[4];
    const float* w_out = (const float*)d_in[5];
    const float* b_out = (const float*)d_in[6];
    float* out = (float*)d_out;

    void *p_hs = nullptr, *p_blk = nullptr;
    cudaGetSymbolAddress(&p_hs, g_hs);
    cudaGetSymbolAddress(&p_blk, g_blk);

    cudaMemsetAsync(p_blk, 0, sizeof(unsigned) * 4 * 2 * 8 * 64);

    const int scan_smem = (4096 * 2 + 256 * RSTR2 + 2048 * 2 + 48 * 257) * 4;  // 135360 B
    cudaFuncSetAttribute(gru_scan, cudaFuncAttributeMaxDynamicSharedMemorySize, scan_smem);

    // Phase 0: transpose x into [s][(g,bh)][k][b8]
    transpose_x<<<S_LEN * 4, 256>>>(x);

    // Phase 1+2: dual-chain fused GRU scan (128 CTAs)
    gru_scan<<<128, 256, scan_smem>>>(w_ih, w_hh, b_ih, b_hh);

    // Phase 3: out = hs @ w_out^T + b_out   (M=32768, N=512, K=512)
    gemm_tn<HID, 1><<<dim3(ODIM / 128, (BATCH * S_LEN) / 128), 256>>>(
        (const float*)p_hs, w_out, b_out, out);
}

// round 8
// speedup vs baseline: 1.1716x; 1.1716x over previous
#include <cuda_runtime.h>
#include <cstring>

#define S_LEN 512
#define BATCH 64
#define IDIM  256
#define HID   512
#define ODIM  512    // 2*O

#define RSTR 68      // sred row stride in floats: 272B = 16B-aligned, conflict-free

// ---------------- scratch (static device globals; no allocation) -------------
__device__ float    g_hsT[(size_t)(S_LEN + 1) * 4 * HID * 16];  // [step][grp][k512][b16]
__device__ float    g_xT [(size_t)S_LEN * 4 * IDIM * 16];       // [s][grp][k256][b16]
__device__ unsigned g_blk[4 * 8 * 64];                          // per-(grp,block) counters

// ---------------- packed f32x2 FMA (full-rate fp32 on sm_100a) ---------------
__device__ __forceinline__ float2 ffma2(float2 a, float2 b, float2 c) {
#if defined(__CUDA_ARCH__) && (__CUDA_ARCH__ >= 1000)
    unsigned long long au, bu, cu, du;
    memcpy(&au, &a, 8); memcpy(&bu, &b, 8); memcpy(&cu, &c, 8);
    asm("fma.rn.f32x2 %0, %1, %2, %3;" : "=l"(du) : "l"(au), "l"(bu), "l"(cu));
    float2 d; memcpy(&d, &du, 8);
    return d;
#else
    return make_float2(fmaf(a.x, b.x, c.x), fmaf(a.y, b.y, c.y));
#endif
}

__device__ __forceinline__ void poll_ge(const unsigned* a, unsigned need) {
    unsigned v;
    do {
        asm volatile("ld.acquire.gpu.global.u32 %0, [%1];" : "=r"(v) : "l"(a) : "memory");
    } while (v < need);
}

__device__ __forceinline__ float fast_sigmoid(float x) {
    return __fdividef(1.f, 1.f + __expf(-x));
}
__device__ __forceinline__ float fast_tanh(float x) {
    return __fdividef(2.f, 1.f + __expf(-2.f * x)) - 1.f;
}

// =============================================================================
// Prologue: x[b][s][k] -> g_xT[s][grp][k][b16]  (smem transpose, coalesced)
// =============================================================================
__global__ __launch_bounds__(256)
void transpose_x(const float* __restrict__ x)
{
    __shared__ float ts[16 * 260];
    const int tid = threadIdx.x;
    const int sg  = blockIdx.x;          // s*4 + grp
    const int s   = sg >> 2, grp = sg & 3;
    const int bb  = tid >> 4, kq = tid & 15;

    const float* src = x + ((size_t)(grp * 16 + bb) * S_LEN + s) * IDIM + kq * 16;
#pragma unroll
    for (int i = 0; i < 4; i++)
        *(float4*)(ts + bb * 260 + kq * 16 + 4 * i) = *(const float4*)(src + 4 * i);
    __syncthreads();

    float* dst = g_xT + ((size_t)sg * 256 + tid) * 16;
#pragma unroll
    for (int q = 0; q < 4; q++) {
        float4 o;
        o.x = ts[(4 * q + 0) * 260 + tid];
        o.y = ts[(4 * q + 1) * 260 + tid];
        o.z = ts[(4 * q + 2) * 260 + tid];
        o.w = ts[(4 * q + 3) * 260 + tid];
        *(float4*)(dst + 4 * q) = o;
    }
}

// =============================================================================
// Output GEMM reading hs straight from g_hsT (no g_hs buffer / scatter store).
// out[(b*512+s)*512+n] = sum_h hs[s][b][h]*w_out[n][h] + b_out[n]
// A-tile (16k x 128m) staged from g_hsT[(s+1)*4+grp][k][b16]: m = (sL*4+grp)*16+b16.
// =============================================================================
__global__ __launch_bounds__(256, 2)
void gemm_out(const float* __restrict__ hsT, const float* __restrict__ B,
              const float* __restrict__ bias, float* __restrict__ C)
{
    __shared__ float As[16 * 132];
    __shared__ float Bs[16 * 132];

    const int tid = threadIdx.x;
    const int m0 = blockIdx.y * 128;     // 128 m-rows = 2 s-values x 64 batches
    const int n0 = blockIdx.x * 128;
    const int s0 = m0 >> 6;

    // B staging ids (w_out, row-major over K=HID)
    const int lr = tid >> 2, lc = tid & 3;
    // A staging ids: unit u covers (k=ak, seg=(sL,grp)), 16 floats; 2 threads/unit
    const int au   = tid >> 1;
    const int ak   = au >> 3;
    const int aseg = au & 7;
    const int asl  = aseg >> 2, agrp = aseg & 3;
    const int aq   = (tid & 1) * 8;
    const int tx = tid & 15, ty = tid >> 4;

    const float* Bp  = B + (size_t)(n0 + lr) * HID + lc * 4;
    const float* Apb = hsT + (((size_t)(s0 + asl + 1) * 4 + agrp) * 8192) + ak * 16 + aq;

    float2 c2[8][4];
#pragma unroll
    for (int i = 0; i < 8; i++)
#pragma unroll
        for (int j = 0; j < 4; j++) c2[i][j] = make_float2(0.f, 0.f);

    float4 pa0 = *(const float4*)(Apb);
    float4 pa1 = *(const float4*)(Apb + 4);
    float4 pb0 = *(const float4*)(Bp);
    float4 pb1 = *(const float4*)(Bp + (size_t)64 * HID);

    const int KT = HID / 16;             // 32
    for (int kt = 0; kt < KT; kt++) {
        // stage A: As[k][m], m contiguous straight from [k][b16] layout
        *(float4*)&As[ak * 132 + aseg * 16 + aq]     = pa0;
        *(float4*)&As[ak * 132 + aseg * 16 + aq + 4] = pa1;
        // stage B transposed
        {
            const float* b0 = (const float*)&pb0;
            const float* b1 = (const float*)&pb1;
#pragma unroll
            for (int j = 0; j < 4; j++) {
                Bs[(lc * 4 + j) * 132 + lr]      = b0[j];
                Bs[(lc * 4 + j) * 132 + lr + 64] = b1[j];
            }
        }
        __syncthreads();
        if (kt + 1 < KT) {
            Apb += 256;                  // next 16 k-rows (16 k * 16 floats)
            Bp  += 16;
            pa0 = *(const float4*)(Apb);
            pa1 = *(const float4*)(Apb + 4);
            pb0 = *(const float4*)(Bp);
            pb1 = *(const float4*)(Bp + (size_t)64 * HID);
        }
#pragma unroll
        for (int k = 0; k < 16; k++) {
            float4 a0 = *(const float4*)&As[k * 132 + ty * 4];
            float4 a1 = *(const float4*)&As[k * 132 + 64 + ty * 4];
            float4 b0 = *(const float4*)&Bs[k * 132 + tx * 4];
            float4 b1 = *(const float4*)&Bs[k * 132 + 64 + tx * 4];
            float av[8] = {a0.x, a0.y, a0.z, a0.w, a1.x, a1.y, a1.z, a1.w};
            float2 bv[4] = {{b0.x, b0.y}, {b0.z, b0.w}, {b1.x, b1.y}, {b1.z, b1.w}};
#pragma unroll
            for (int i = 0; i < 8; i++) {
                float2 ad = make_float2(av[i], av[i]);
#pragma unroll
                for (int j = 0; j < 4; j++) c2[i][j] = ffma2(ad, bv[j], c2[i][j]);
            }
        }
        __syncthreads();
    }

    int ncol[4];
    float2 bb[4];
#pragma unroll
    for (int j = 0; j < 4; j++) {
        ncol[j] = n0 + ((j < 2) ? (tx * 4 + 2 * j) : (64 + tx * 4 + 2 * (j - 2)));
        bb[j] = make_float2(bias[ncol[j]], bias[ncol[j] + 1]);
    }

#pragma unroll
    for (int i = 0; i < 8; i++) {
        int r = m0 + ((i < 4) ? (ty * 4 + i) : (64 + ty * 4 + (i - 4)));
        int s = r >> 6, b = r & 63;
        size_t rbase = ((size_t)(b * S_LEN + s)) * ODIM;
#pragma unroll
        for (int j = 0; j < 4; j++) {
            float2 v = make_float2(c2[i][j].x + bb[j].x, c2[i][j].y + bb[j].y);
            *(float2*)&C[rbase + ncol[j]] = v;
        }
    }
}

// =============================================================================
// Fused GRU scan (R6 structure): 4 groups x 32 CTAs; slice = 16 j; w_hh in
// registers, w_ih in SMEM. Warp-parallel exchange (warp w = block w, per-block
// monotonic counters). Only ONE global store per thread per step (exchange).
// =============================================================================
__global__ __launch_bounds__(256, 1)
void gru_scan(const float* __restrict__ w_ih, const float* __restrict__ w_hh,
              const float* __restrict__ b_ih, const float* __restrict__ b_hh)
{
    extern __shared__ float sm[];
    float* sh_h = sm;                      // 8192  : h [k512][b16]
    float* sred = sm + 8192;               // 17408 : partials 256 x RSTR
    float* sx   = sm + 8192 + 17408;       // 8192  : x tiles, 2 x [k256][b16]
    float* sw   = sx + 8192;               // 12336 : w_ih slice [48][257]

    const int tid     = threadIdx.x;
    const int lane    = tid & 31;
    const int wrp     = tid >> 5;          // warp id = exchange block id
    const int grp     = blockIdx.x >> 5;
    const int slice   = blockIdx.x & 31;
    const int j0      = slice * 16;
    const int own_blk = slice >> 2;
    const int kI      = tid >> 4;          // k-chunk id 0..15
    const int jI      = tid & 15;          // hidden unit in slice
    const int jj      = kI;                // gate-stage hidden idx
    const int bbat    = jI;                // gate-stage batch idx

    // ---- w_hh register-resident (k = kI + 16*m) ----------------------------
    float w[3][32];
#pragma unroll
    for (int g = 0; g < 3; g++) {
        const float* p = w_hh + (size_t)(g * HID + j0 + jI) * HID + kI;
#pragma unroll
        for (int m = 0; m < 32; m++) w[g][m] = p[16 * m];
    }

    // ---- stage w_ih slice into SMEM (rows (g,j), pad 257) ------------------
    for (int i = tid; i < 48 * 256; i += 256) {
        int row = i >> 8, k = i & 255;
        int g = row >> 4, jr = row & 15;
        sw[row * 257 + k] = w_ih[(size_t)(g * HID + j0 + jr) * IDIM + k];
    }

    // ---- fused biases ------------------------------------------------------
    const float bR  = b_ih[j0 + jj]           + b_hh[j0 + jj];
    const float bZ  = b_ih[HID + j0 + jj]     + b_hh[HID + j0 + jj];
    const float bIN = b_ih[2 * HID + j0 + jj];
    const float bHN = b_hh[2 * HID + j0 + jj];

    for (int i = tid; i < 8192; i += 256) sh_h[i] = 0.f;   // h_0 = 0
    {   // stage x tile for step 0
        const float4* src = (const float4*)(g_xT + (size_t)grp * 4096);
        float4* dst = (float4*)sx;
#pragma unroll
        for (int i = 0; i < 4; i++) dst[tid + 256 * i] = src[tid + 256 * i];
    }
    __syncthreads();

    for (int s = 0; s < S_LEN; s++) {
        float2 acc[8][4];
#pragma unroll
        for (int p = 0; p < 8; p++)
#pragma unroll
            for (int g = 0; g < 4; g++) acc[p][g] = make_float2(0.f, 0.f);

        const float* xrow = sx + (s & 1) * 4096 + kI * 256;
        const float* swr = sw + jI * 257        + kI * 16;
        const float* swz = sw + (16 + jI) * 257 + kI * 16;
        const float* swn = sw + (32 + jI) * 257 + kI * 16;

        // ---- gi chunk A (kk 0..7) -----------------------------------------
#pragma unroll 4
        for (int kk = 0; kk < 8; kk++) {
            float wr = swr[kk], wz = swz[kk], wn = swn[kk];
            float2 WR = {wr, wr}, WZ = {wz, wz}, WN = {wn, wn};
            const float* xr = xrow + kk * 16;
#pragma unroll
            for (int q = 0; q < 4; q++) {
                float4 x4 = *(const float4*)(xr + 4 * q);
                float2 x01 = {x4.x, x4.y}, x23 = {x4.z, x4.w};
                acc[2 * q][0]     = ffma2(x01, WR, acc[2 * q][0]);
                acc[2 * q][1]     = ffma2(x01, WZ, acc[2 * q][1]);
                acc[2 * q][3]     = ffma2(x01, WN, acc[2 * q][3]);
                acc[2 * q + 1][0] = ffma2(x23, WR, acc[2 * q + 1][0]);
                acc[2 * q + 1][1] = ffma2(x23, WZ, acc[2 * q + 1][1]);
                acc[2 * q + 1][3] = ffma2(x23, WN, acc[2 * q + 1][3]);
            }
        }

        // ---- poll (fast path) + LDG h --------------------------------------
        float4 h0, h1, h2, h3, h4, h5, h6, h7;
        if (s > 0) {
            if (lane == 0) poll_ge(&g_blk[(grp * 8 + wrp) * 64], 4u * (unsigned)s);
            __syncwarp();
            const float4* srcb = (const float4*)(g_hsT + ((size_t)s * 4 + grp) * 8192)
                                 + wrp * 256 + lane;
            h0 = srcb[0];   h1 = srcb[32];  h2 = srcb[64];  h3 = srcb[96];
            h4 = srcb[128]; h5 = srcb[160]; h6 = srcb[192]; h7 = srcb[224];
        }

        // ---- gi chunk B (kk 8..15) — hides h LDG latency -------------------
#pragma unroll 4
        for (int kk = 8; kk < 16; kk++) {
            float wr = swr[kk], wz = swz[kk], wn = swn[kk];
            float2 WR = {wr, wr}, WZ = {wz, wz}, WN = {wn, wn};
            const float* xr = xrow + kk * 16;
#pragma unroll
            for (int q = 0; q < 4; q++) {
                float4 x4 = *(const float4*)(xr + 4 * q);
                float2 x01 = {x4.x, x4.y}, x23 = {x4.z, x4.w};
                acc[2 * q][0]     = ffma2(x01, WR, acc[2 * q][0]);
                acc[2 * q][1]     = ffma2(x01, WZ, acc[2 * q][1]);
                acc[2 * q][3]     = ffma2(x01, WN, acc[2 * q][3]);
                acc[2 * q + 1][0] = ffma2(x23, WR, acc[2 * q + 1][0]);
                acc[2 * q + 1][1] = ffma2(x23, WZ, acc[2 * q + 1][1]);
                acc[2 * q + 1][3] = ffma2(x23, WN, acc[2 * q + 1][3]);
            }
        }

        if (s > 0) {
            float4* dstb = (float4*)sh_h + wrp * 256 + lane;
            dstb[0]   = h0; dstb[32]  = h1; dstb[64]  = h2; dstb[96]  = h3;
            dstb[128] = h4; dstb[160] = h5; dstb[192] = h6; dstb[224] = h7;
        }
        __syncthreads();

        // ---- gh-FMA over full 512 k (planes 0,1,2) -------------------------
        if (s > 0) {
#pragma unroll
            for (int m = 0; m < 32; m++) {
                const float* hr = sh_h + (kI + 16 * m) * 16;
                float2 WR = {w[0][m], w[0][m]};
                float2 WZ = {w[1][m], w[1][m]};
                float2 WN = {w[2][m], w[2][m]};
#pragma unroll
                for (int q = 0; q < 4; q++) {
                    float4 h4v = *(const float4*)(hr + 4 * q);
                    float2 h01 = {h4v.x, h4v.y}, h23 = {h4v.z, h4v.w};
                    acc[2 * q][0]     = ffma2(h01, WR, acc[2 * q][0]);
                    acc[2 * q][1]     = ffma2(h01, WZ, acc[2 * q][1]);
                    acc[2 * q][2]     = ffma2(h01, WN, acc[2 * q][2]);
                    acc[2 * q + 1][0] = ffma2(h23, WR, acc[2 * q + 1][0]);
                    acc[2 * q + 1][1] = ffma2(h23, WZ, acc[2 * q + 1][1]);
                    acc[2 * q + 1][2] = ffma2(h23, WN, acc[2 * q + 1][2]);
                }
            }
        }

        // ---- dump: 16 waste-free STS.128 -----------------------------------
        {
            float* rp = sred + tid * RSTR;
#pragma unroll
            for (int p = 0; p < 8; p++) {
                *(float4*)(rp + 8 * p)     =
                    make_float4(acc[p][0].x, acc[p][1].x, acc[p][2].x, acc[p][3].x);
                *(float4*)(rp + 8 * p + 4) =
                    make_float4(acc[p][0].y, acc[p][1].y, acc[p][2].y, acc[p][3].y);
            }
        }
        __syncthreads();

        // ---- x prefetch for s+1 (consumed after reduce) --------------------
        float4 xf0, xf1, xf2, xf3;
        if (s + 1 < S_LEN) {
            const float4* xsrc = (const float4*)(g_xT + ((size_t)(s + 1) * 4 + grp) * 4096);
            xf0 = xsrc[tid]; xf1 = xsrc[tid + 256]; xf2 = xsrc[tid + 512]; xf3 = xsrc[tid + 768];
        }

        // ---- reduce + gates -------------------------------------------------
        float R = bR, Z = bZ, GN = 0.f, GI = bIN;
#pragma unroll
        for (int kc = 0; kc < 16; kc++) {
            float4 v = *(const float4*)(sred + (kc * 16 + jj) * RSTR + 4 * bbat);
            R += v.x; Z += v.y; GN += v.z; GI += v.w;
        }
        float r = fast_sigmoid(R);
        float z = fast_sigmoid(Z);
        float n = fast_tanh(GI + r * (GN + bHN));
        float hp = sh_h[(j0 + jj) * 16 + bbat];
        float hn = (1.f - z) * n + z * hp;

        // ONLY global store on the critical loop: contiguous exchange write
        g_hsT[((size_t)(s + 1) * 4 + grp) * 8192 + (j0 + jj) * 16 + bbat] = hn;

        if (s + 1 < S_LEN) {
            float4* xd = (float4*)(sx + ((s + 1) & 1) * 4096);
            xd[tid] = xf0; xd[tid + 256] = xf1; xd[tid + 512] = xf2; xd[tid + 768] = xf3;
        }
        __syncthreads();   // h + x tile visible before release / next gi

        if (tid == 0) {
            unsigned* ctr = &g_blk[(grp * 8 + own_blk) * 64];
            asm volatile("red.release.gpu.global.add.u32 [%0], 1;" :: "l"(ctr) : "memory");
        }
    }
}

// =============================================================================
extern "C" void kernel_launch(void* const* d_in, const int* in_sizes, int n_in,
                              void* d_out, int out_size)
{
    (void)in_sizes; (void)n_in; (void)out_size;
    const float* x     = (const float*)d_in[0];
    const float* w_ih  = (const float*)d_in[1];
    const float* w_hh  = (const float*)d_in[2];
    const float* b_ih  = (const float*)d_in[3];
    const float* b_hh  = (const float*)d_in[4];
    const float* w_out = (const float*)d_in[5];
    const float* b_out = (const float*)d_in[6];
    float* out = (float*)d_out;

    void *p_hsT = nullptr, *p_blk = nullptr;
    cudaGetSymbolAddress(&p_hsT, g_hsT);
    cudaGetSymbolAddress(&p_blk, g_blk);

    cudaMemsetAsync(p_blk, 0, sizeof(unsigned) * 4 * 8 * 64);

    const int scan_smem = (8192 + 256 * RSTR + 8192 + 48 * 257) * 4;   // 184512 B
    cudaFuncSetAttribute(gru_scan, cudaFuncAttributeMaxDynamicSharedMemorySize, scan_smem);

    // Phase 0: transpose x into [s][grp][k][b16]
    transpose_x<<<S_LEN * 4, 256>>>(x);

    // Phase 1+2: fused GRU scan (128 CTAs, warp-parallel exchange)
    gru_scan<<<128, 256, scan_smem>>>(w_ih, w_hh, b_ih, b_hh);

    // Phase 3: out = hs @ w_out^T + b_out, A read directly from g_hsT
    gemm_out<<<dim3(ODIM / 128, (BATCH * S_LEN) / 128), 256>>>(
        (const float*)p_hsT, w_out, b_out, out);
}